// round 3
// baseline (speedup 1.0000x reference)
#include <cuda_runtime.h>

// Fixed shapes for SPHERE_CUDA_77163382440039
static constexpr int HW     = 512 * 512;   // 262144 HT cells
static constexpr int NCH    = 128;         // flat channels (B4 * C4)
static constexpr int S      = 32768;       // sphere bins
static constexpr int RANGE  = 64;          // HT cells per bucket range
static constexpr int NRANGE = HW / RANGE;  // 4096 ranges
static constexpr int CAPR   = 768;         // capacity per range (Poisson(366): 768 ~ 21 sigma)

// Scratch (static __device__ — no runtime allocation)
__device__ __align__(16) float  g_outT[(size_t)S * NCH];          // [s][ch], 16.8 MB (L2-resident)
__device__ __align__(16) float2 g_bucket[(size_t)NRANGE * CAPR];  // packed(h_local,s), weight — 25 MB
__device__ int g_cursor[NRANGE];

// ---------------------------------------------------------------------------
// Zero the [s][ch] accumulator and the range cursors in one kernel.
__global__ void zero_kernel() {
    int i = blockIdx.x * blockDim.x + threadIdx.x;
    if (i < S * NCH / 4)
        reinterpret_cast<float4*>(g_outT)[i] = make_float4(0.f, 0.f, 0.f, 0.f);
    if (i < NRANGE) g_cursor[i] = 0;
}

// ---------------------------------------------------------------------------
// Bucket votes by 64-cell HT range. One thread per vote.
__global__ void scatter_kernel(const int* __restrict__ ht_idx,
                               const int* __restrict__ sp_idx,
                               const float* __restrict__ weight,
                               int nvotes) {
    int v = blockIdx.x * blockDim.x + threadIdx.x;
    if (v >= nvotes) return;
    int h      = ht_idx[v];
    int r      = h >> 6;                         // range id
    int packed = ((h & 63) << 15) | sp_idx[v];   // h_local[6b] | s[15b]
    int pos    = atomicAdd(&g_cursor[r], 1);
    if (pos < CAPR)
        g_bucket[(size_t)r * CAPR + pos] =
            make_float2(__int_as_float(packed), weight[v]);
}

// ---------------------------------------------------------------------------
// One block per HT range: stage the [64 hw][128 ch] x tile in smem (transposed
// on the fly from the original [ch][hw] layout), then for each vote in the
// range, warp-gather the 512B row from smem and vector-RED into L2-resident
// g_outT[s][ch]. Column rotation (float4-granular) keeps writes ~2-way
// conflicted and reads conflict-free + 16B-aligned.
__global__ __launch_bounds__(256) void accum_kernel(const float* __restrict__ x) {
    __shared__ float sm[64 * 132];               // 33.8 KB, rows padded to 132
    const int r  = blockIdx.x;
    const int h0 = r * RANGE;
    const int t  = threadIdx.x;

    // Stage tile: thread t handles float4 #(k*256+t): ch = idx>>4, i4 = idx&15.
    // Global read: 16 lanes cover one channel's 256B run — fully coalesced.
    #pragma unroll
    for (int k = 0; k < 8; k++) {
        int idx4 = k * 256 + t;
        int ch   = idx4 >> 4;
        int i4   = idx4 & 15;
        float4 v = *reinterpret_cast<const float4*>(
            &x[(size_t)ch * HW + h0 + i4 * 4]);
        int col = (ch + ((i4 & 7) << 2)) & 127;  // float4-granular rotation
        sm[(i4 * 4 + 0) * 132 + col] = v.x;
        sm[(i4 * 4 + 1) * 132 + col] = v.y;
        sm[(i4 * 4 + 2) * 132 + col] = v.z;
        sm[(i4 * 4 + 3) * 132 + col] = v.w;
    }
    __syncthreads();

    int n = g_cursor[r];
    if (n > CAPR) n = CAPR;
    const float2* __restrict__ rec = &g_bucket[(size_t)r * CAPR];
    const int lane = t & 31;
    const int warp = t >> 5;

    for (int i = warp; i < n; i += 8) {
        float2 rc  = __ldg(&rec[i]);             // uniform address: broadcast
        int packed = __float_as_int(rc.x);
        int hl     = packed >> 15;
        int s      = packed & 32767;
        float wt   = rc.y;
        int rot    = ((hl >> 2) & 7) << 2;       // must match the write rotation
        const float4 xv = *reinterpret_cast<const float4*>(
            &sm[hl * 132 + ((lane * 4 + rot) & 127)]);
        asm volatile(
            "red.global.add.v4.f32 [%0], {%1, %2, %3, %4};"
            :: "l"(&g_outT[(size_t)s * NCH + lane * 4]),
               "f"(xv.x * wt), "f"(xv.y * wt), "f"(xv.z * wt), "f"(xv.w * wt)
            : "memory");
    }
}

// ---------------------------------------------------------------------------
// 32x32 tiled transpose: out[c][r] = in[r][c], in is [R][C]. R,C % 32 == 0.
__global__ void transpose_kernel(const float* __restrict__ in,
                                 float* __restrict__ out,
                                 int R, int C) {
    __shared__ float tile[32][33];
    int c  = blockIdx.x * 32 + threadIdx.x;
    int r0 = blockIdx.y * 32;
    #pragma unroll
    for (int j = 0; j < 32; j += 8) {
        tile[threadIdx.y + j][threadIdx.x] =
            in[(size_t)(r0 + threadIdx.y + j) * C + c];
    }
    __syncthreads();
    int r  = r0 + threadIdx.x;
    int c0 = blockIdx.x * 32;
    #pragma unroll
    for (int j = 0; j < 32; j += 8) {
        out[(size_t)(c0 + threadIdx.y + j) * R + r] =
            tile[threadIdx.x][threadIdx.y + j];
    }
}

// ---------------------------------------------------------------------------
extern "C" void kernel_launch(void* const* d_in, const int* in_sizes, int n_in,
                              void* d_out, int out_size) {
    const float* x      = (const float*)d_in[0];  // [128][262144] flat
    const int*   ht     = (const int*)d_in[1];
    const int*   sp     = (const int*)d_in[2];
    const float* w      = (const float*)d_in[3];
    float*       out    = (float*)d_out;          // [128][32768] flat
    const int    nvotes = in_sizes[1];

    void* outT_p = nullptr;
    cudaGetSymbolAddress(&outT_p, g_outT);

    // 1) Zero accumulator + cursors.
    zero_kernel<<<(S * NCH / 4 + 255) / 256, 256>>>();

    // 2) Bucket votes by HT range.
    scatter_kernel<<<(nvotes + 255) / 256, 256>>>(ht, sp, w, nvotes);

    // 3) Per-range smem-staged accumulation with L2-resident vector REDs.
    accum_kernel<<<NRANGE, 256>>>(x);

    // 4) Transpose g_outT [S][128] -> out [128][S].
    {
        dim3 grid(NCH / 32, S / 32);   // (4, 1024)
        dim3 block(32, 8);
        transpose_kernel<<<grid, block>>>((const float*)outT_p, out, S, NCH);
    }
}

// round 4
// speedup vs baseline: 1.2575x; 1.2575x over previous
#include <cuda_runtime.h>
#include <cuda_fp16.h>

// Fixed shapes for SPHERE_CUDA_77163382440039
static constexpr int HW  = 512 * 512;   // 262144 HT cells
static constexpr int NCH = 128;         // flat channels (B4 * C4)
static constexpr int S   = 32768;       // sphere bins
static constexpr int CAP = 128;         // bucket capacity per bin (Poisson(45.8))

// Scratch (static __device__ — no runtime allocation)
__device__ __align__(16) __half g_xTh[(size_t)HW * NCH];     // x transposed [hw][ch], fp16, 67 MB
__device__ __align__(16) float2 g_bucket[(size_t)S * CAP];   // (h bits, weight) per bin, 33.5 MB
__device__ int g_cursor[S];

// ---------------------------------------------------------------------------
__global__ void zero_cursor_kernel() {
    int i = blockIdx.x * blockDim.x + threadIdx.x;
    if (i < S) g_cursor[i] = 0;
}

// ---------------------------------------------------------------------------
// Transpose + convert: x [128][HW] fp32 -> g_xTh [HW][128] fp16.
// 32x32 tiles; reads are 128B runs, writes are 64B runs (full 32B sectors).
__global__ void transpose_convert_kernel(const float* __restrict__ in) {
    __shared__ float tile[32][33];
    int c  = blockIdx.x * 32 + threadIdx.x;   // hw index
    int r0 = blockIdx.y * 32;                 // ch base
    #pragma unroll
    for (int j = 0; j < 32; j += 8) {
        tile[threadIdx.y + j][threadIdx.x] =
            in[(size_t)(r0 + threadIdx.y + j) * HW + c];
    }
    __syncthreads();
    int hw = blockIdx.x * 32 + threadIdx.x;   // reuse tx as hw-in-tile
    #pragma unroll
    for (int j = 0; j < 32; j += 8) {
        // write g_xTh[hw][ch] for ch = r0 + ty + j ... wait: need per-thread hw
        // Standard scheme: thread (tx,ty+j) writes element (ch = r0+tx? ) — use
        // the classic mapping: output row index = blockIdx.x*32 + ty + j (hw),
        // column = r0 + tx (ch).
    }
    // Classic transposed write (recomputed cleanly):
    int ch = r0 + threadIdx.x;
    int h0 = blockIdx.x * 32;
    #pragma unroll
    for (int j = 0; j < 32; j += 8) {
        g_xTh[(size_t)(h0 + threadIdx.y + j) * NCH + ch] =
            __float2half_rn(tile[threadIdx.x][threadIdx.y + j]);
    }
}

// ---------------------------------------------------------------------------
// Bucket votes by sphere bin: one thread per vote.
__global__ void scatter_kernel(const int* __restrict__ ht_idx,
                               const int* __restrict__ sp_idx,
                               const float* __restrict__ weight,
                               int nvotes) {
    int v = blockIdx.x * blockDim.x + threadIdx.x;
    if (v >= nvotes) return;
    int s   = sp_idx[v];
    int pos = atomicAdd(&g_cursor[s], 1);
    if (pos < CAP) {
        g_bucket[(size_t)s * CAP + pos] =
            make_float2(__int_as_float(ht_idx[v]), weight[v]);
    }
}

// ---------------------------------------------------------------------------
// One warp per sphere bin; lane l accumulates channels [4l, 4l+4) in fp32.
// Gather = 256B fp16 rows (mostly L2-hit: table is L2-resident at 67MB).
// 8 bins/block; smem-staged fused output transpose; zero atomics on output.
__global__ __launch_bounds__(256) void accum_kernel(float* __restrict__ out) {
    const int warp = threadIdx.x >> 5;
    const int lane = threadIdx.x & 31;
    const int s    = blockIdx.x * 8 + warp;

    int n = g_cursor[s];
    if (n > CAP) n = CAP;
    const float2* __restrict__ rec = &g_bucket[(size_t)s * CAP];

    float4 a0 = make_float4(0.f, 0.f, 0.f, 0.f);
    float4 a1 = make_float4(0.f, 0.f, 0.f, 0.f);

    int i = 0;
    for (; i + 2 <= n; i += 2) {
        float2 r0 = rec[i];
        float2 r1 = rec[i + 1];
        const uint2 p0 = *reinterpret_cast<const uint2*>(
            &g_xTh[(size_t)__float_as_int(r0.x) * NCH + lane * 4]);
        const uint2 p1 = *reinterpret_cast<const uint2*>(
            &g_xTh[(size_t)__float_as_int(r1.x) * NCH + lane * 4]);
        float2 f0a = __half22float2(*reinterpret_cast<const __half2*>(&p0.x));
        float2 f0b = __half22float2(*reinterpret_cast<const __half2*>(&p0.y));
        float2 f1a = __half22float2(*reinterpret_cast<const __half2*>(&p1.x));
        float2 f1b = __half22float2(*reinterpret_cast<const __half2*>(&p1.y));
        a0.x += f0a.x * r0.y; a0.y += f0a.y * r0.y;
        a0.z += f0b.x * r0.y; a0.w += f0b.y * r0.y;
        a1.x += f1a.x * r1.y; a1.y += f1a.y * r1.y;
        a1.z += f1b.x * r1.y; a1.w += f1b.y * r1.y;
    }
    if (i < n) {
        float2 r0 = rec[i];
        const uint2 p0 = *reinterpret_cast<const uint2*>(
            &g_xTh[(size_t)__float_as_int(r0.x) * NCH + lane * 4]);
        float2 f0a = __half22float2(*reinterpret_cast<const __half2*>(&p0.x));
        float2 f0b = __half22float2(*reinterpret_cast<const __half2*>(&p0.y));
        a0.x += f0a.x * r0.y; a0.y += f0a.y * r0.y;
        a0.z += f0b.x * r0.y; a0.w += f0b.y * r0.y;
    }
    a0.x += a1.x; a0.y += a1.y; a0.z += a1.z; a0.w += a1.w;

    // Stage [8 bins][128 ch] in smem, then write out[ch][s0..s0+7] coalesced.
    __shared__ float sm[8][128];
    *reinterpret_cast<float4*>(&sm[warp][lane * 4]) = a0;
    __syncthreads();

    if (threadIdx.x < 128) {
        const int ch = threadIdx.x;
        const int s0 = blockIdx.x * 8;
        float4 o0 = make_float4(sm[0][ch], sm[1][ch], sm[2][ch], sm[3][ch]);
        float4 o1 = make_float4(sm[4][ch], sm[5][ch], sm[6][ch], sm[7][ch]);
        float4* dst = reinterpret_cast<float4*>(&out[(size_t)ch * S + s0]);
        dst[0] = o0;
        dst[1] = o1;
    }
}

// ---------------------------------------------------------------------------
extern "C" void kernel_launch(void* const* d_in, const int* in_sizes, int n_in,
                              void* d_out, int out_size) {
    const float* x      = (const float*)d_in[0];  // [128][262144] flat
    const int*   ht     = (const int*)d_in[1];
    const int*   sp     = (const int*)d_in[2];
    const float* w      = (const float*)d_in[3];
    float*       out    = (float*)d_out;          // [128][32768] flat
    const int    nvotes = in_sizes[1];

    // 1) Zero bucket cursors.
    zero_cursor_kernel<<<(S + 255) / 256, 256>>>();

    // 2) Transpose + fp16-convert x -> g_xTh [HW][128].
    {
        dim3 grid(HW / 32, NCH / 32);   // (8192, 4)
        dim3 block(32, 8);
        transpose_convert_kernel<<<grid, block>>>(x);
    }

    // 3) Bucket votes by sphere bin.
    scatter_kernel<<<(nvotes + 255) / 256, 256>>>(ht, sp, w, nvotes);

    // 4) Per-bin register accumulation (fp16 gather, fp32 accum) + fused
    //    output transpose.
    accum_kernel<<<S / 8, 256>>>(out);
}

// round 5
// speedup vs baseline: 1.4677x; 1.1671x over previous
#include <cuda_runtime.h>
#include <cuda_fp16.h>

// Fixed shapes for SPHERE_CUDA_77163382440039
static constexpr int HW  = 512 * 512;   // 262144 HT cells
static constexpr int NCH = 128;         // flat channels (B4 * C4)
static constexpr int S   = 32768;       // sphere bins
static constexpr int CAP = 128;         // bucket capacity per bin (Poisson(45.8))

// Scratch (static __device__ — no runtime allocation)
__device__ __align__(16) __half g_xTh[(size_t)HW * NCH];     // x transposed [hw][ch], fp16, 67 MB
__device__ __align__(16) float2 g_bucket[(size_t)S * CAP];   // (h bits, weight) per bin, 33.5 MB
__device__ int g_cursor[S];

// ---------------------------------------------------------------------------
__global__ void zero_cursor_kernel() {
    int i = blockIdx.x * blockDim.x + threadIdx.x;
    if (i < S) g_cursor[i] = 0;
}

// ---------------------------------------------------------------------------
// Vectorized transpose + convert: x [128][HW] fp32 -> g_xTh [HW][128] fp16.
// Tile = 32 ch x 128 hw. float4 global reads (512B warp runs), pad-129 smem
// (conflict-free both phases), __half2-pair (8B) stores forming 64B runs.
__global__ __launch_bounds__(256) void transpose_convert_kernel(const float* __restrict__ in) {
    __shared__ float tile[32 * 129];
    const int t  = threadIdx.x;
    const int h0 = blockIdx.x * 128;
    const int r0 = blockIdx.y * 32;

    // Read: iter k covers ch rows [k*8, k*8+8); lane pattern = 512B runs.
    #pragma unroll
    for (int k = 0; k < 4; k++) {
        int ch_l = (t >> 5) + k * 8;
        int hw4  = t & 31;
        float4 v = *reinterpret_cast<const float4*>(
            &in[(size_t)(r0 + ch_l) * HW + h0 + hw4 * 4]);
        float* dst = &tile[ch_l * 129 + hw4 * 4];
        dst[0] = v.x; dst[1] = v.y; dst[2] = v.z; dst[3] = v.w;
    }
    __syncthreads();

    // Write: thread handles 4 ch values of one hw row -> uint2 (4 halves).
    #pragma unroll
    for (int k = 0; k < 4; k++) {
        int hw_l = (t >> 3) + k * 32;
        int chg  = t & 7;
        __half2 lo = __floats2half2_rn(tile[(chg * 4 + 0) * 129 + hw_l],
                                       tile[(chg * 4 + 1) * 129 + hw_l]);
        __half2 hi = __floats2half2_rn(tile[(chg * 4 + 2) * 129 + hw_l],
                                       tile[(chg * 4 + 3) * 129 + hw_l]);
        uint2 pk;
        pk.x = *reinterpret_cast<const unsigned*>(&lo);
        pk.y = *reinterpret_cast<const unsigned*>(&hi);
        *reinterpret_cast<uint2*>(
            &g_xTh[(size_t)(h0 + hw_l) * NCH + r0 + chg * 4]) = pk;
    }
}

// ---------------------------------------------------------------------------
// Bucket votes by sphere bin: one thread per vote.
__global__ void scatter_kernel(const int* __restrict__ ht_idx,
                               const int* __restrict__ sp_idx,
                               const float* __restrict__ weight,
                               int nvotes) {
    int v = blockIdx.x * blockDim.x + threadIdx.x;
    if (v >= nvotes) return;
    int s   = sp_idx[v];
    int pos = atomicAdd(&g_cursor[s], 1);
    if (pos < CAP) {
        g_bucket[(size_t)s * CAP + pos] =
            make_float2(__int_as_float(ht_idx[v]), weight[v]);
    }
}

// ---------------------------------------------------------------------------
// One warp per sphere bin; lane l owns channels [4l, 4l+4) in fp32 registers.
// Unroll-4: two float4 record loads + 4 independent 8B row-gathers in flight
// per iteration (MLP >= 4 against ~250cyc L2-hit latency).
// 8 bins/block; smem-staged fused output transpose; zero output atomics.
__global__ __launch_bounds__(256) void accum_kernel(float* __restrict__ out) {
    const int warp = threadIdx.x >> 5;
    const int lane = threadIdx.x & 31;
    const int s    = blockIdx.x * 8 + warp;

    int n = g_cursor[s];
    if (n > CAP) n = CAP;
    const float2* __restrict__ rec  = &g_bucket[(size_t)s * CAP];
    const float4* __restrict__ rec4 = reinterpret_cast<const float4*>(rec);
    const size_t col = (size_t)(lane * 4);

    float4 a0 = make_float4(0.f, 0.f, 0.f, 0.f);
    float4 a1 = make_float4(0.f, 0.f, 0.f, 0.f);

    int i = 0;
    for (; i + 4 <= n; i += 4) {
        float4 ra = rec4[(i >> 1) + 0];   // records i, i+1: (h,w,h,w)
        float4 rb = rec4[(i >> 1) + 1];   // records i+2, i+3
        const uint2 p0 = *reinterpret_cast<const uint2*>(
            &g_xTh[(size_t)__float_as_int(ra.x) * NCH + col]);
        const uint2 p1 = *reinterpret_cast<const uint2*>(
            &g_xTh[(size_t)__float_as_int(ra.z) * NCH + col]);
        const uint2 p2 = *reinterpret_cast<const uint2*>(
            &g_xTh[(size_t)__float_as_int(rb.x) * NCH + col]);
        const uint2 p3 = *reinterpret_cast<const uint2*>(
            &g_xTh[(size_t)__float_as_int(rb.z) * NCH + col]);

        float2 f;
        f = __half22float2(*reinterpret_cast<const __half2*>(&p0.x));
        a0.x += f.x * ra.y; a0.y += f.y * ra.y;
        f = __half22float2(*reinterpret_cast<const __half2*>(&p0.y));
        a0.z += f.x * ra.y; a0.w += f.y * ra.y;

        f = __half22float2(*reinterpret_cast<const __half2*>(&p1.x));
        a1.x += f.x * ra.w; a1.y += f.y * ra.w;
        f = __half22float2(*reinterpret_cast<const __half2*>(&p1.y));
        a1.z += f.x * ra.w; a1.w += f.y * ra.w;

        f = __half22float2(*reinterpret_cast<const __half2*>(&p2.x));
        a0.x += f.x * rb.y; a0.y += f.y * rb.y;
        f = __half22float2(*reinterpret_cast<const __half2*>(&p2.y));
        a0.z += f.x * rb.y; a0.w += f.y * rb.y;

        f = __half22float2(*reinterpret_cast<const __half2*>(&p3.x));
        a1.x += f.x * rb.w; a1.y += f.y * rb.w;
        f = __half22float2(*reinterpret_cast<const __half2*>(&p3.y));
        a1.z += f.x * rb.w; a1.w += f.y * rb.w;
    }
    for (; i < n; i++) {
        float2 r0 = rec[i];
        const uint2 p0 = *reinterpret_cast<const uint2*>(
            &g_xTh[(size_t)__float_as_int(r0.x) * NCH + col]);
        float2 f;
        f = __half22float2(*reinterpret_cast<const __half2*>(&p0.x));
        a0.x += f.x * r0.y; a0.y += f.y * r0.y;
        f = __half22float2(*reinterpret_cast<const __half2*>(&p0.y));
        a0.z += f.x * r0.y; a0.w += f.y * r0.y;
    }
    a0.x += a1.x; a0.y += a1.y; a0.z += a1.z; a0.w += a1.w;

    // Stage [8 bins][128 ch] in smem, then write out[ch][s0..s0+7] coalesced.
    __shared__ float sm[8][128];
    *reinterpret_cast<float4*>(&sm[warp][lane * 4]) = a0;
    __syncthreads();

    if (threadIdx.x < 128) {
        const int ch = threadIdx.x;
        const int s0 = blockIdx.x * 8;
        float4 o0 = make_float4(sm[0][ch], sm[1][ch], sm[2][ch], sm[3][ch]);
        float4 o1 = make_float4(sm[4][ch], sm[5][ch], sm[6][ch], sm[7][ch]);
        float4* dst = reinterpret_cast<float4*>(&out[(size_t)ch * S + s0]);
        dst[0] = o0;
        dst[1] = o1;
    }
}

// ---------------------------------------------------------------------------
extern "C" void kernel_launch(void* const* d_in, const int* in_sizes, int n_in,
                              void* d_out, int out_size) {
    const float* x      = (const float*)d_in[0];  // [128][262144] flat
    const int*   ht     = (const int*)d_in[1];
    const int*   sp     = (const int*)d_in[2];
    const float* w      = (const float*)d_in[3];
    float*       out    = (float*)d_out;          // [128][32768] flat
    const int    nvotes = in_sizes[1];

    // 1) Zero bucket cursors.
    zero_cursor_kernel<<<(S + 255) / 256, 256>>>();

    // 2) Vectorized transpose + fp16-convert x -> g_xTh [HW][128].
    {
        dim3 grid(HW / 128, NCH / 32);   // (2048, 4)
        transpose_convert_kernel<<<grid, 256>>>(x);
    }

    // 3) Bucket votes by sphere bin.
    scatter_kernel<<<(nvotes + 255) / 256, 256>>>(ht, sp, w, nvotes);

    // 4) Per-bin register accumulation (fp16 gather, fp32 accum, MLP=4)
    //    + fused output transpose.
    accum_kernel<<<S / 8, 256>>>(out);
}

// round 6
// speedup vs baseline: 1.5871x; 1.0814x over previous
#include <cuda_runtime.h>
#include <cuda_fp16.h>

// Fixed shapes for SPHERE_CUDA_77163382440039
static constexpr int HW  = 512 * 512;   // 262144 HT cells
static constexpr int NCH = 128;         // flat channels (B4 * C4)
static constexpr int S   = 32768;       // sphere bins
static constexpr int CAP = 128;         // bucket capacity per bin (Poisson(45.8))

// Scratch (static __device__ — no runtime allocation)
__device__ __align__(16) __half g_xTh[(size_t)HW * NCH];     // x transposed [hw][ch], fp16, 67 MB
__device__ __align__(16) float2 g_bucket[(size_t)S * CAP];   // (h bits, weight) per bin, 33.5 MB
__device__ int g_cursor[S];

// ---------------------------------------------------------------------------
__global__ void zero_cursor_kernel() {
    int i = blockIdx.x * blockDim.x + threadIdx.x;
    if (i < S) g_cursor[i] = 0;
}

// ---------------------------------------------------------------------------
// Transpose + convert: x [128][HW] fp32 -> g_xTh [HW][128] fp16.
// Tile = 32 ch x 128 hw. Phase 1: float4 global reads (512B warp runs) ->
// conflict-free 16B smem stores at XOR-swizzled column (hw4 ^ 2*(ch>>3)).
// Phase 2: conflict-free scalar smem reads (bank bijection verified) -> pack
// 8 halves -> 16B global stores forming 64B full-sector runs.
__global__ __launch_bounds__(256) void transpose_convert_kernel(const float* __restrict__ in) {
    __shared__ float4 tile4[32][32];    // 16 KB, [ch][swizzled hw4]
    const int t  = threadIdx.x;
    const int h0 = blockIdx.x * 128;
    const int r0 = blockIdx.y * 32;

    #pragma unroll
    for (int k = 0; k < 4; k++) {
        int ch_l = (t >> 5) + k * 8;
        int hw4  = t & 31;
        float4 v = *reinterpret_cast<const float4*>(
            &in[(size_t)(r0 + ch_l) * HW + h0 + hw4 * 4]);
        tile4[ch_l][hw4 ^ (((ch_l >> 3) & 3) << 1)] = v;
    }
    __syncthreads();

    const float* tf = reinterpret_cast<const float*>(tile4);
    #pragma unroll
    for (int k = 0; k < 2; k++) {
        int chg  = t & 3;                               // group of 8 channels
        int hw_l = (t >> 5) * 8 + ((t & 31) >> 2) + k * 64;
        int swz  = (chg << 1);                          // 2*((chg*8+j)>>3) = 2*chg
        int col  = ((hw_l >> 2) ^ swz) * 4 + (hw_l & 3);
        float f0 = tf[(chg * 8 + 0) * 128 + col];
        float f1 = tf[(chg * 8 + 1) * 128 + col];
        float f2 = tf[(chg * 8 + 2) * 128 + col];
        float f3 = tf[(chg * 8 + 3) * 128 + col];
        float f4 = tf[(chg * 8 + 4) * 128 + col];
        float f5 = tf[(chg * 8 + 5) * 128 + col];
        float f6 = tf[(chg * 8 + 6) * 128 + col];
        float f7 = tf[(chg * 8 + 7) * 128 + col];
        __half2 h0p = __floats2half2_rn(f0, f1);
        __half2 h1p = __floats2half2_rn(f2, f3);
        __half2 h2p = __floats2half2_rn(f4, f5);
        __half2 h3p = __floats2half2_rn(f6, f7);
        uint4 pk;
        pk.x = *reinterpret_cast<const unsigned*>(&h0p);
        pk.y = *reinterpret_cast<const unsigned*>(&h1p);
        pk.z = *reinterpret_cast<const unsigned*>(&h2p);
        pk.w = *reinterpret_cast<const unsigned*>(&h3p);
        *reinterpret_cast<uint4*>(
            &g_xTh[(size_t)(h0 + hw_l) * NCH + r0 + chg * 8]) = pk;
    }
}

// ---------------------------------------------------------------------------
// Bucket votes by sphere bin: one thread per vote.
__global__ void scatter_kernel(const int* __restrict__ ht_idx,
                               const int* __restrict__ sp_idx,
                               const float* __restrict__ weight,
                               int nvotes) {
    int v = blockIdx.x * blockDim.x + threadIdx.x;
    if (v >= nvotes) return;
    int s   = sp_idx[v];
    int pos = atomicAdd(&g_cursor[s], 1);
    if (pos < CAP) {
        g_bucket[(size_t)s * CAP + pos] =
            make_float2(__int_as_float(ht_idx[v]), weight[v]);
    }
}

// ---------------------------------------------------------------------------
// One warp per sphere bin; lane l owns channels [4l, 4l+4) in fp32 registers.
// Unroll-8: four float4 record loads + 8 independent 8B row-gathers in flight
// per iteration. 8 bins/block; smem-staged fused output transpose; no atomics.
__global__ __launch_bounds__(256) void accum_kernel(float* __restrict__ out) {
    const int warp = threadIdx.x >> 5;
    const int lane = threadIdx.x & 31;
    const int s    = blockIdx.x * 8 + warp;

    int n = g_cursor[s];
    if (n > CAP) n = CAP;
    const float2* __restrict__ rec  = &g_bucket[(size_t)s * CAP];
    const float4* __restrict__ rec4 = reinterpret_cast<const float4*>(rec);
    const size_t col = (size_t)(lane * 4);

    float4 a0 = make_float4(0.f, 0.f, 0.f, 0.f);
    float4 a1 = make_float4(0.f, 0.f, 0.f, 0.f);

    int i = 0;
    for (; i + 8 <= n; i += 8) {
        float4 ra = rec4[(i >> 1) + 0];
        float4 rb = rec4[(i >> 1) + 1];
        float4 rc = rec4[(i >> 1) + 2];
        float4 rd = rec4[(i >> 1) + 3];
        const uint2 p0 = *reinterpret_cast<const uint2*>(
            &g_xTh[(size_t)__float_as_int(ra.x) * NCH + col]);
        const uint2 p1 = *reinterpret_cast<const uint2*>(
            &g_xTh[(size_t)__float_as_int(ra.z) * NCH + col]);
        const uint2 p2 = *reinterpret_cast<const uint2*>(
            &g_xTh[(size_t)__float_as_int(rb.x) * NCH + col]);
        const uint2 p3 = *reinterpret_cast<const uint2*>(
            &g_xTh[(size_t)__float_as_int(rb.z) * NCH + col]);
        const uint2 p4 = *reinterpret_cast<const uint2*>(
            &g_xTh[(size_t)__float_as_int(rc.x) * NCH + col]);
        const uint2 p5 = *reinterpret_cast<const uint2*>(
            &g_xTh[(size_t)__float_as_int(rc.z) * NCH + col]);
        const uint2 p6 = *reinterpret_cast<const uint2*>(
            &g_xTh[(size_t)__float_as_int(rd.x) * NCH + col]);
        const uint2 p7 = *reinterpret_cast<const uint2*>(
            &g_xTh[(size_t)__float_as_int(rd.z) * NCH + col]);

        float2 f;
        f = __half22float2(*reinterpret_cast<const __half2*>(&p0.x));
        a0.x += f.x * ra.y; a0.y += f.y * ra.y;
        f = __half22float2(*reinterpret_cast<const __half2*>(&p0.y));
        a0.z += f.x * ra.y; a0.w += f.y * ra.y;
        f = __half22float2(*reinterpret_cast<const __half2*>(&p1.x));
        a1.x += f.x * ra.w; a1.y += f.y * ra.w;
        f = __half22float2(*reinterpret_cast<const __half2*>(&p1.y));
        a1.z += f.x * ra.w; a1.w += f.y * ra.w;

        f = __half22float2(*reinterpret_cast<const __half2*>(&p2.x));
        a0.x += f.x * rb.y; a0.y += f.y * rb.y;
        f = __half22float2(*reinterpret_cast<const __half2*>(&p2.y));
        a0.z += f.x * rb.y; a0.w += f.y * rb.y;
        f = __half22float2(*reinterpret_cast<const __half2*>(&p3.x));
        a1.x += f.x * rb.w; a1.y += f.y * rb.w;
        f = __half22float2(*reinterpret_cast<const __half2*>(&p3.y));
        a1.z += f.x * rb.w; a1.w += f.y * rb.w;

        f = __half22float2(*reinterpret_cast<const __half2*>(&p4.x));
        a0.x += f.x * rc.y; a0.y += f.y * rc.y;
        f = __half22float2(*reinterpret_cast<const __half2*>(&p4.y));
        a0.z += f.x * rc.y; a0.w += f.y * rc.y;
        f = __half22float2(*reinterpret_cast<const __half2*>(&p5.x));
        a1.x += f.x * rc.w; a1.y += f.y * rc.w;
        f = __half22float2(*reinterpret_cast<const __half2*>(&p5.y));
        a1.z += f.x * rc.w; a1.w += f.y * rc.w;

        f = __half22float2(*reinterpret_cast<const __half2*>(&p6.x));
        a0.x += f.x * rd.y; a0.y += f.y * rd.y;
        f = __half22float2(*reinterpret_cast<const __half2*>(&p6.y));
        a0.z += f.x * rd.y; a0.w += f.y * rd.y;
        f = __half22float2(*reinterpret_cast<const __half2*>(&p7.x));
        a1.x += f.x * rd.w; a1.y += f.y * rd.w;
        f = __half22float2(*reinterpret_cast<const __half2*>(&p7.y));
        a1.z += f.x * rd.w; a1.w += f.y * rd.w;
    }
    for (; i < n; i++) {
        float2 r0 = rec[i];
        const uint2 p0 = *reinterpret_cast<const uint2*>(
            &g_xTh[(size_t)__float_as_int(r0.x) * NCH + col]);
        float2 f;
        f = __half22float2(*reinterpret_cast<const __half2*>(&p0.x));
        a0.x += f.x * r0.y; a0.y += f.y * r0.y;
        f = __half22float2(*reinterpret_cast<const __half2*>(&p0.y));
        a0.z += f.x * r0.y; a0.w += f.y * r0.y;
    }
    a0.x += a1.x; a0.y += a1.y; a0.z += a1.z; a0.w += a1.w;

    // Stage [8 bins][128 ch] in smem, then write out[ch][s0..s0+7] coalesced.
    __shared__ float sm[8][128];
    *reinterpret_cast<float4*>(&sm[warp][lane * 4]) = a0;
    __syncthreads();

    if (threadIdx.x < 128) {
        const int ch = threadIdx.x;
        const int s0 = blockIdx.x * 8;
        float4 o0 = make_float4(sm[0][ch], sm[1][ch], sm[2][ch], sm[3][ch]);
        float4 o1 = make_float4(sm[4][ch], sm[5][ch], sm[6][ch], sm[7][ch]);
        float4* dst = reinterpret_cast<float4*>(&out[(size_t)ch * S + s0]);
        dst[0] = o0;
        dst[1] = o1;
    }
}

// ---------------------------------------------------------------------------
extern "C" void kernel_launch(void* const* d_in, const int* in_sizes, int n_in,
                              void* d_out, int out_size) {
    const float* x      = (const float*)d_in[0];  // [128][262144] flat
    const int*   ht     = (const int*)d_in[1];
    const int*   sp     = (const int*)d_in[2];
    const float* w      = (const float*)d_in[3];
    float*       out    = (float*)d_out;          // [128][32768] flat
    const int    nvotes = in_sizes[1];

    // 1) Zero bucket cursors.
    zero_cursor_kernel<<<(S + 255) / 256, 256>>>();

    // 2) Swizzled transpose + fp16-convert x -> g_xTh [HW][128].
    {
        dim3 grid(HW / 128, NCH / 32);   // (2048, 4)
        transpose_convert_kernel<<<grid, 256>>>(x);
    }

    // 3) Bucket votes by sphere bin.
    scatter_kernel<<<(nvotes + 255) / 256, 256>>>(ht, sp, w, nvotes);

    // 4) Per-bin register accumulation (fp16 gather, fp32 accum, MLP=8)
    //    + fused output transpose.
    accum_kernel<<<S / 8, 256>>>(out);
}